// round 11
// baseline (speedup 1.0000x reference)
#include <cuda_runtime.h>
#include <cstdint>

#define BATCH 8
#define SEQ   2048
#define DIM   64
#define TM    64
#define TN    64
#define NTILES 32
#define NTHR  128

// ---- smem layout (float offsets) ----
#define KST  68
#define VST  72
#define EST  68
#define KBUF (64*KST)            // 4352
#define VBUF (64*VST)            // 4608
#define F_K   0
#define F_V   (F_K + 2*KBUF)     // 8704
#define F_SE  (F_V + 2*VBUF)     // 17920
#define F_MSK (F_SE + TM*EST)    // 22272
#define F_INV (F_MSK + SEQ)      // 24320
#define SMEM_FLOATS (F_INV + TM) // 24384
#define SMEM_BYTES (SMEM_FLOATS*4)

__device__ __forceinline__ uint32_t tf32u(float x) {
    uint32_t u; asm("cvt.rna.tf32.f32 %0, %1;" : "=r"(u) : "f"(x)); return u;
}
__device__ __forceinline__ float uf(uint32_t u) { return __uint_as_float(u); }
__device__ __forceinline__ uint32_t fu(float f) { return __float_as_uint(f); }
__device__ __forceinline__ uint32_t s2u(const void* p) {
    uint32_t a;
    asm("{ .reg .u64 t; cvta.to.shared.u64 t, %1; cvt.u32.u64 %0, t; }" : "=r"(a) : "l"(p));
    return a;
}

#define CP16(dst, src) asm volatile("cp.async.ca.shared.global [%0], [%1], 16;" \
                                    :: "r"(dst), "l"(src) : "memory")
#define CP_COMMIT() asm volatile("cp.async.commit_group;" ::: "memory")
#define CP_WAIT0()  asm volatile("cp.async.wait_group 0;" ::: "memory")

// D += A(16x8 tf32) * B(8x8 tf32), fp32 accumulate
__device__ __forceinline__ void mma8(float* c, const uint32_t* a, uint32_t b0, uint32_t b1) {
    asm volatile("mma.sync.aligned.m16n8k8.row.col.f32.tf32.tf32.f32 "
        "{%0,%1,%2,%3},{%4,%5,%6,%7},{%8,%9},{%0,%1,%2,%3};"
        : "+f"(c[0]), "+f"(c[1]), "+f"(c[2]), "+f"(c[3])
        : "r"(a[0]), "r"(a[1]), "r"(a[2]), "r"(a[3]), "r"(b0), "r"(b1));
}

// stage raw K,V tile nt via cp.async into buffer nt&1
__device__ __forceinline__ void stage(uint32_t sb, const float* kgb, const float* vgb,
                                      int nt, int t) {
    const int buf = nt & 1;
    const float* kg = kgb + (size_t)nt * TN * DIM;
    const float* vg = vgb + (size_t)nt * TN * DIM;
    uint32_t kdst = sb + (F_K + buf * KBUF) * 4;
    uint32_t vdst = sb + (F_V + buf * VBUF) * 4;
    #pragma unroll
    for (int it = 0; it < 8; it++) {
        int idx = t + NTHR * it;          // float4 index in 64x64 tile
        int row = idx >> 4, c = (idx & 15) * 4;
        CP16(kdst + (row * KST + c) * 4, kg + idx * 4);
        CP16(vdst + (row * VST + c) * 4, vg + idx * 4);
    }
}

__global__ void __launch_bounds__(NTHR, 2)
attn_mma_kernel(const float* __restrict__ key,
                const float* __restrict__ query,
                const float* __restrict__ value,
                const int*   __restrict__ qmask,
                float* __restrict__ out_ctx,
                float*              out_attn)
{
    extern __shared__ float sm[];
    const uint32_t sb = s2u(sm);
    const int b  = blockIdx.y;
    const int q0 = blockIdx.x * TM;
    const int t  = threadIdx.x;
    const int wq = t >> 5;          // warp 0..3 -> q rows 16*wq..+15
    const int lane = t & 31;
    const int r4 = lane >> 2;       // 0..7
    const int c4 = lane & 3;        // 0..3

    const float* kg_base = key   + (size_t)b * SEQ * DIM;
    const float* vg_base = value + (size_t)b * SEQ * DIM;
    float* attn_base = out_attn + ((size_t)b * SEQ + q0) * SEQ;

    // ---- stage tile 0 (async), mask ----
    stage(sb, kg_base, vg_base, 0, t);
    CP_COMMIT();
    {
        const int* mg = qmask + (size_t)b * SEQ;
        float* msk = sm + F_MSK;
        for (int i = t; i < SEQ; i += NTHR)
            msk[i] = mg[i] ? -1e30f : 0.0f;
    }

    // ---- persistent Q frags (hi/lo), scaled by 0.125 ----
    uint32_t qh[8][4], ql[8][4];
    {
        const float* qr = query + ((size_t)b * SEQ + q0 + 16 * wq) * DIM;
        #pragma unroll
        for (int ks = 0; ks < 8; ks++) {
            float x0 = qr[(size_t)r4 * DIM + ks * 8 + c4] * 0.125f;
            float x1 = qr[(size_t)(r4 + 8) * DIM + ks * 8 + c4] * 0.125f;
            float x2 = qr[(size_t)r4 * DIM + ks * 8 + c4 + 4] * 0.125f;
            float x3 = qr[(size_t)(r4 + 8) * DIM + ks * 8 + c4 + 4] * 0.125f;
            qh[ks][0] = tf32u(x0); ql[ks][0] = fu(x0 - uf(qh[ks][0]));
            qh[ks][1] = tf32u(x1); ql[ks][1] = fu(x1 - uf(qh[ks][1]));
            qh[ks][2] = tf32u(x2); ql[ks][2] = fu(x2 - uf(qh[ks][2]));
            qh[ks][3] = tf32u(x3); ql[ks][3] = fu(x3 - uf(qh[ks][3]));
        }
    }

    float cacc[4][2][4];            // ctx^T frags [mt][nq][4]
    #pragma unroll
    for (int mt = 0; mt < 4; mt++)
        #pragma unroll
        for (int nq = 0; nq < 2; nq++)
            #pragma unroll
            for (int i = 0; i < 4; i++) cacc[mt][nq][i] = 0.0f;
    float rs0 = 0.0f, rs8 = 0.0f;

    float* sE = sm + F_SE;
    const float* msk = sm + F_MSK;

    for (int kt = 0; kt < NTILES; kt++) {
        const int buf = kt & 1;
        CP_WAIT0();
        __syncthreads();            // tile kt ready; prev compute done everywhere
        if (kt + 1 < NTILES) {
            stage(sb, kg_base, vg_base, kt + 1, t);
            CP_COMMIT();
        }

        // ---- QK^T: S[16q x 64key], 3xTF32, on-the-fly hi/lo split of K ----
        float sacc[8][4];
        #pragma unroll
        for (int nt = 0; nt < 8; nt++)
            #pragma unroll
            for (int i = 0; i < 4; i++) sacc[nt][i] = 0.0f;

        const float* kraw = sm + F_K + buf * KBUF + r4 * KST + c4;
        #pragma unroll
        for (int ks = 0; ks < 8; ks++) {
            #pragma unroll
            for (int nt = 0; nt < 8; nt++) {
                const float* p = kraw + nt * 8 * KST + ks * 8;
                float x0 = p[0], x1 = p[4];
                uint32_t b0h = tf32u(x0), b1h = tf32u(x1);
                uint32_t b0l = fu(x0 - uf(b0h)), b1l = fu(x1 - uf(b1h));
                mma8(sacc[nt], qh[ks], b0h, b1h);
                mma8(sacc[nt], qh[ks], b0l, b1l);
                mma8(sacc[nt], ql[ks], b0h, b1h);
            }
        }

        // ---- epilogue: exp+mask, e -> gmem (float2) + sE, rowsum ----
        {
            float* ar0 = attn_base + (size_t)(16 * wq + r4) * SEQ + kt * 64;
            float* ar8 = ar0 + (size_t)8 * SEQ;
            float* se0 = sE + (16 * wq + r4) * EST;
            float* se8 = se0 + 8 * EST;
            #pragma unroll
            for (int nt = 0; nt < 8; nt++) {
                int kloc = nt * 8 + 2 * c4;
                float m0 = msk[kt * 64 + kloc];
                float m1 = msk[kt * 64 + kloc + 1];
                float e0 = __expf(sacc[nt][0] + m0);
                float e1 = __expf(sacc[nt][1] + m1);
                float e2 = __expf(sacc[nt][2] + m0);
                float e3 = __expf(sacc[nt][3] + m1);
                rs0 += e0 + e1; rs8 += e2 + e3;
                *(float2*)(ar0 + kloc) = make_float2(e0, e1);
                *(float2*)(ar8 + kloc) = make_float2(e2, e3);
                *(float2*)(se0 + kloc) = make_float2(e0, e1);
                *(float2*)(se8 + kloc) = make_float2(e2, e3);
            }
        }
        __syncwarp();

        // ---- PV (transposed): ctx^T += V^T * P^T, on-the-fly hi/lo of V ----
        {
            const float* vraw = sm + F_V + buf * VBUF + c4 * VST + r4;
            const float* se_b = sE + (16 * wq + r4) * EST + c4;
            #pragma unroll
            for (int ks = 0; ks < 8; ks++) {
                uint32_t bh[2][2], bl[2][2];
                #pragma unroll
                for (int nq = 0; nq < 2; nq++) {
                    float p0 = se_b[nq * 8 * EST + ks * 8];
                    float p1 = se_b[nq * 8 * EST + ks * 8 + 4];
                    bh[nq][0] = tf32u(p0); bl[nq][0] = fu(p0 - uf(bh[nq][0]));
                    bh[nq][1] = tf32u(p1); bl[nq][1] = fu(p1 - uf(bh[nq][1]));
                }
                #pragma unroll
                for (int mt = 0; mt < 4; mt++) {
                    const float* p = vraw + ks * 8 * VST + mt * 16;
                    float x0 = p[0], x1 = p[8], x2 = p[4 * VST], x3 = p[4 * VST + 8];
                    uint32_t ah[4], al[4];
                    ah[0] = tf32u(x0); al[0] = fu(x0 - uf(ah[0]));
                    ah[1] = tf32u(x1); al[1] = fu(x1 - uf(ah[1]));
                    ah[2] = tf32u(x2); al[2] = fu(x2 - uf(ah[2]));
                    ah[3] = tf32u(x3); al[3] = fu(x3 - uf(ah[3]));
                    #pragma unroll
                    for (int nq = 0; nq < 2; nq++) {
                        mma8(cacc[mt][nq], ah, bh[nq][0], bh[nq][1]);
                        mma8(cacc[mt][nq], ah, bl[nq][0], bl[nq][1]);
                        mma8(cacc[mt][nq], al, bh[nq][0], bh[nq][1]);
                    }
                }
            }
        }
    }

    // ---- rowsum reduce (quad shfl), write inv ----
    rs0 += __shfl_xor_sync(0xffffffffu, rs0, 1);
    rs0 += __shfl_xor_sync(0xffffffffu, rs0, 2);
    rs8 += __shfl_xor_sync(0xffffffffu, rs8, 1);
    rs8 += __shfl_xor_sync(0xffffffffu, rs8, 2);
    if (c4 == 0) {
        sm[F_INV + 16 * wq + r4]     = 1.0f / rs0;
        sm[F_INV + 16 * wq + r4 + 8] = 1.0f / rs8;
    }
    __syncthreads();

    // ---- ctx out (normalized) ----
    {
        const float* sInv = sm + F_INV;
        #pragma unroll
        for (int nq = 0; nq < 2; nq++) {
            int qloc = 16 * wq + nq * 8 + 2 * c4;
            float i0 = sInv[qloc], i1 = sInv[qloc + 1];
            float* o0 = out_ctx + ((size_t)b * SEQ + q0 + qloc) * DIM;
            float* o1 = o0 + DIM;
            #pragma unroll
            for (int mt = 0; mt < 4; mt++) {
                int dimr = mt * 16 + r4;
                o0[dimr]     = cacc[mt][nq][0] * i0;
                o1[dimr]     = cacc[mt][nq][1] * i1;
                o0[dimr + 8] = cacc[mt][nq][2] * i0;
                o1[dimr + 8] = cacc[mt][nq][3] * i1;
            }
        }
    }

    // ---- normalize this CTA's attn slab in place (L2-hot) ----
    {
        const float* sInv = sm + F_INV;
        #pragma unroll 4
        for (int i = t; i < TM * SEQ / 4; i += NTHR) {
            int r = i >> 9;            // / (SEQ/4)
            int c = i & 511;
            float inv = sInv[r];
            float4* p = (float4*)(attn_base + (size_t)r * SEQ) + c;
            float4 v = *p;
            v.x *= inv; v.y *= inv; v.z *= inv; v.w *= inv;
            *p = v;
        }
    }
}

extern "C" void kernel_launch(void* const* d_in, const int* in_sizes, int n_in,
                              void* d_out, int out_size)
{
    const float* key   = (const float*)d_in[0];
    const float* query = (const float*)d_in[1];
    const float* value = (const float*)d_in[2];
    const int*   qmask = (const int*)d_in[3];

    float* out_ctx  = (float*)d_out;
    float* out_attn = (float*)d_out + (size_t)BATCH * SEQ * DIM;

    cudaFuncSetAttribute(attn_mma_kernel,
                         cudaFuncAttributeMaxDynamicSharedMemorySize, SMEM_BYTES);

    dim3 grid(SEQ / TM, BATCH);
    attn_mma_kernel<<<grid, NTHR, SMEM_BYTES>>>(key, query, value, qmask,
                                                out_ctx, out_attn);
}

// round 12
// speedup vs baseline: 1.1606x; 1.1606x over previous
#include <cuda_runtime.h>
#include <cstdint>

#define BATCH 8
#define SEQ   2048
#define DIM   64
#define TM    128
#define TN    64
#define NTILES 32
#define NTHR  256

// ---- smem layout (float offsets) ----
#define KST  68
#define VST  72
#define EST  68
#define KBUF (64*KST)          // 4352
#define VBUF (64*VST)          // 4608
#define F_KHI 0
#define F_KLO (F_KHI + 2*KBUF) // 8704
#define F_VHI (F_KLO + 2*KBUF) // 17408
#define F_VLO (F_VHI + 2*VBUF) // 26624
#define F_SE  (F_VLO + 2*VBUF) // 35840
#define F_MSK (F_SE + TM*EST)  // 44544
#define F_INV (F_MSK + SEQ)    // 46592
#define SMEM_FLOATS (F_INV + TM) // 46720
#define SMEM_BYTES (SMEM_FLOATS*4)

__device__ __forceinline__ uint32_t tf32u(float x) {
    uint32_t u; asm("cvt.rna.tf32.f32 %0, %1;" : "=r"(u) : "f"(x)); return u;
}
__device__ __forceinline__ float uf(uint32_t u) { return __uint_as_float(u); }
__device__ __forceinline__ uint32_t fu(float f) { return __float_as_uint(f); }

// D += A(16x8 tf32) * B(8x8 tf32), fp32 accumulate
__device__ __forceinline__ void mma8(float* c, const uint32_t* a, uint32_t b0, uint32_t b1) {
    asm volatile("mma.sync.aligned.m16n8k8.row.col.f32.tf32.tf32.f32 "
        "{%0,%1,%2,%3},{%4,%5,%6,%7},{%8,%9},{%0,%1,%2,%3};"
        : "+f"(c[0]), "+f"(c[1]), "+f"(c[2]), "+f"(c[3])
        : "r"(a[0]), "r"(a[1]), "r"(a[2]), "r"(a[3]), "r"(b0), "r"(b1));
}

__device__ __forceinline__ void storeK(float* sm, int buf, int idx, float4 v) {
    int row = idx >> 4, c = (idx & 15) * 4;
    float4 h, l;
    h.x = uf(tf32u(v.x)); l.x = v.x - h.x;
    h.y = uf(tf32u(v.y)); l.y = v.y - h.y;
    h.z = uf(tf32u(v.z)); l.z = v.z - h.z;
    h.w = uf(tf32u(v.w)); l.w = v.w - h.w;
    *(float4*)(sm + F_KHI + buf*KBUF + row*KST + c) = h;
    *(float4*)(sm + F_KLO + buf*KBUF + row*KST + c) = l;
}
__device__ __forceinline__ void storeV(float* sm, int buf, int idx, float4 v) {
    int row = idx >> 4, c = (idx & 15) * 4;
    float4 h, l;
    h.x = uf(tf32u(v.x)); l.x = v.x - h.x;
    h.y = uf(tf32u(v.y)); l.y = v.y - h.y;
    h.z = uf(tf32u(v.z)); l.z = v.z - h.z;
    h.w = uf(tf32u(v.w)); l.w = v.w - h.w;
    *(float4*)(sm + F_VHI + buf*VBUF + row*VST + c) = h;
    *(float4*)(sm + F_VLO + buf*VBUF + row*VST + c) = l;
}

__global__ void __launch_bounds__(NTHR, 1)
attn_mma_kernel(const float* __restrict__ key,
                const float* __restrict__ query,
                const float* __restrict__ value,
                const int*   __restrict__ qmask,
                float* __restrict__ out_ctx,
                float*              out_attn)
{
    extern __shared__ float sm[];
    const int b  = blockIdx.y;
    const int q0 = blockIdx.x * TM;
    const int t  = threadIdx.x;
    const int wq = t >> 5;          // warp 0..7 -> q rows 16*wq..+15
    const int lane = t & 31;
    const int r4 = lane >> 2;       // 0..7
    const int c4 = lane & 3;        // 0..3

    const float* kg_base = key   + (size_t)b * SEQ * DIM;
    const float* vg_base = value + (size_t)b * SEQ * DIM;
    float* attn_base = out_attn + ((size_t)b * SEQ + q0) * SEQ;

    // ---- stage tile 0, mask ----
    {
        const float4* kg = (const float4*)kg_base;
        const float4* vg = (const float4*)vg_base;
        #pragma unroll
        for (int it = 0; it < 4; it++) {
            int idx = t + 256 * it;
            storeK(sm, 0, idx, kg[idx]);
            storeV(sm, 0, idx, vg[idx]);
        }
        const int* mg = qmask + (size_t)b * SEQ;
        float* msk = sm + F_MSK;
        for (int i = t; i < SEQ; i += NTHR)
            msk[i] = mg[i] ? -1e30f : 0.0f;
    }

    // ---- persistent Q frags (hi only; Q pre-scaled by 0.125) ----
    // 2-term scheme: S = Qhi*Khi + Qhi*Klo  (drops Qlo*Khi, ~1.2e-4 rel)
    uint32_t qh[8][4];
    {
        const float* qr = query + ((size_t)b * SEQ + q0 + 16 * wq) * DIM;
        #pragma unroll
        for (int ks = 0; ks < 8; ks++) {
            qh[ks][0] = tf32u(qr[(size_t)r4 * DIM + ks * 8 + c4] * 0.125f);
            qh[ks][1] = tf32u(qr[(size_t)(r4 + 8) * DIM + ks * 8 + c4] * 0.125f);
            qh[ks][2] = tf32u(qr[(size_t)r4 * DIM + ks * 8 + c4 + 4] * 0.125f);
            qh[ks][3] = tf32u(qr[(size_t)(r4 + 8) * DIM + ks * 8 + c4 + 4] * 0.125f);
        }
    }
    __syncthreads();

    float cacc[4][2][4];            // ctx^T frags [mt][nq][4]
    #pragma unroll
    for (int mt = 0; mt < 4; mt++)
        #pragma unroll
        for (int nq = 0; nq < 2; nq++)
            #pragma unroll
            for (int i = 0; i < 4; i++) cacc[mt][nq][i] = 0.0f;
    float rs0 = 0.0f, rs8 = 0.0f;   // rowsums for q rows 16wq+r4, +8

    float* sE = sm + F_SE;
    const float* msk = sm + F_MSK;

    for (int kt = 0; kt < NTILES; kt++) {
        const int buf = kt & 1;
        // ---- prefetch next tile into regs ----
        float4 pk[4], pv[4];
        if (kt + 1 < NTILES) {
            const float4* kg = (const float4*)kg_base + (size_t)(kt + 1) * TN * DIM / 4;
            const float4* vg = (const float4*)vg_base + (size_t)(kt + 1) * TN * DIM / 4;
            #pragma unroll
            for (int it = 0; it < 4; it++) {
                pk[it] = kg[t + 256 * it];
                pv[it] = vg[t + 256 * it];
            }
        }

        // ---- QK^T: S[16q x 64key], 2-term tf32 ----
        float sacc[8][4];
        #pragma unroll
        for (int nt = 0; nt < 8; nt++)
            #pragma unroll
            for (int i = 0; i < 4; i++) sacc[nt][i] = 0.0f;

        const float* kh_b = sm + F_KHI + buf * KBUF + r4 * KST + c4;
        const float* kl_b = sm + F_KLO + buf * KBUF + r4 * KST + c4;
        #pragma unroll
        for (int ks = 0; ks < 8; ks++) {
            #pragma unroll
            for (int nt = 0; nt < 8; nt++) {
                const float* ph = kh_b + nt * 8 * KST + ks * 8;
                const float* pl = kl_b + nt * 8 * KST + ks * 8;
                uint32_t b0h = fu(ph[0]), b1h = fu(ph[4]);
                uint32_t b0l = fu(pl[0]), b1l = fu(pl[4]);
                mma8(sacc[nt], qh[ks], b0h, b1h);
                mma8(sacc[nt], qh[ks], b0l, b1l);
            }
        }

        // ---- epilogue: exp+mask, e -> gmem (float2) + sE, rowsum ----
        {
            float* ar0 = attn_base + (size_t)(16 * wq + r4) * SEQ + kt * 64;
            float* ar8 = ar0 + (size_t)8 * SEQ;
            float* se0 = sE + (16 * wq + r4) * EST;
            float* se8 = se0 + 8 * EST;
            #pragma unroll
            for (int nt = 0; nt < 8; nt++) {
                int kloc = nt * 8 + 2 * c4;
                float m0 = msk[kt * 64 + kloc];
                float m1 = msk[kt * 64 + kloc + 1];
                float e0 = __expf(sacc[nt][0] + m0);
                float e1 = __expf(sacc[nt][1] + m1);
                float e2 = __expf(sacc[nt][2] + m0);
                float e3 = __expf(sacc[nt][3] + m1);
                rs0 += e0 + e1; rs8 += e2 + e3;
                *(float2*)(ar0 + kloc) = make_float2(e0, e1);
                *(float2*)(ar8 + kloc) = make_float2(e2, e3);
                *(float2*)(se0 + kloc) = make_float2(e0, e1);
                *(float2*)(se8 + kloc) = make_float2(e2, e3);
            }
        }
        __syncwarp();

        // ---- PV (transposed): ctx^T = (Vhi+Vlo)^T * Phi^T, 2-term tf32 ----
        // (drops Vhi*Plo term, ~1.2e-4 rel)
        {
            const float* vh_b = sm + F_VHI + buf * VBUF + c4 * VST + r4;
            const float* vl_b = sm + F_VLO + buf * VBUF + c4 * VST + r4;
            const float* se_b = sE + (16 * wq + r4) * EST + c4;
            #pragma unroll
            for (int ks = 0; ks < 8; ks++) {
                uint32_t bh[2][2];
                #pragma unroll
                for (int nq = 0; nq < 2; nq++) {
                    bh[nq][0] = tf32u(se_b[nq * 8 * EST + ks * 8]);
                    bh[nq][1] = tf32u(se_b[nq * 8 * EST + ks * 8 + 4]);
                }
                #pragma unroll
                for (int mt = 0; mt < 4; mt++) {
                    const float* ah_p = vh_b + ks * 8 * VST + mt * 16;
                    const float* al_p = vl_b + ks * 8 * VST + mt * 16;
                    uint32_t ah[4], al[4];
                    ah[0] = fu(ah_p[0]);           al[0] = fu(al_p[0]);
                    ah[1] = fu(ah_p[8]);           al[1] = fu(al_p[8]);
                    ah[2] = fu(ah_p[4 * VST]);     al[2] = fu(al_p[4 * VST]);
                    ah[3] = fu(ah_p[4 * VST + 8]); al[3] = fu(al_p[4 * VST + 8]);
                    #pragma unroll
                    for (int nq = 0; nq < 2; nq++) {
                        mma8(cacc[mt][nq], ah, bh[nq][0], bh[nq][1]);
                        mma8(cacc[mt][nq], al, bh[nq][0], bh[nq][1]);
                    }
                }
            }
        }

        // ---- store prefetched tile into other buffer ----
        if (kt + 1 < NTILES) {
            const int buf2 = (kt + 1) & 1;
            #pragma unroll
            for (int it = 0; it < 4; it++) {
                int idx = t + 256 * it;
                storeK(sm, buf2, idx, pk[it]);
                storeV(sm, buf2, idx, pv[it]);
            }
        }
        __syncthreads();
    }

    // ---- rowsum reduce (quad shfl), write inv ----
    rs0 += __shfl_xor_sync(0xffffffffu, rs0, 1);
    rs0 += __shfl_xor_sync(0xffffffffu, rs0, 2);
    rs8 += __shfl_xor_sync(0xffffffffu, rs8, 1);
    rs8 += __shfl_xor_sync(0xffffffffu, rs8, 2);
    if (c4 == 0) {
        sm[F_INV + 16 * wq + r4]     = 1.0f / rs0;
        sm[F_INV + 16 * wq + r4 + 8] = 1.0f / rs8;
    }
    __syncthreads();

    // ---- ctx out (normalized) ----
    {
        const float* sInv = sm + F_INV;
        #pragma unroll
        for (int nq = 0; nq < 2; nq++) {
            int qloc = 16 * wq + nq * 8 + 2 * c4;
            float i0 = sInv[qloc], i1 = sInv[qloc + 1];
            float* o0 = out_ctx + ((size_t)b * SEQ + q0 + qloc) * DIM;
            float* o1 = o0 + DIM;
            #pragma unroll
            for (int mt = 0; mt < 4; mt++) {
                int dimr = mt * 16 + r4;
                o0[dimr]     = cacc[mt][nq][0] * i0;
                o1[dimr]     = cacc[mt][nq][1] * i1;
                o0[dimr + 8] = cacc[mt][nq][2] * i0;
                o1[dimr + 8] = cacc[mt][nq][3] * i1;
            }
        }
    }

    // ---- normalize this CTA's attn slab in place (L2-hot) ----
    {
        const float* sInv = sm + F_INV;
        #pragma unroll 4
        for (int i = t; i < TM * SEQ / 4; i += NTHR) {
            int r = i >> 9;            // / (SEQ/4)
            int c = i & 511;
            float inv = sInv[r];
            float4* p = (float4*)(attn_base + (size_t)r * SEQ) + c;
            float4 v = *p;
            v.x *= inv; v.y *= inv; v.z *= inv; v.w *= inv;
            *p = v;
        }
    }
}

extern "C" void kernel_launch(void* const* d_in, const int* in_sizes, int n_in,
                              void* d_out, int out_size)
{
    const float* key   = (const float*)d_in[0];
    const float* query = (const float*)d_in[1];
    const float* value = (const float*)d_in[2];
    const int*   qmask = (const int*)d_in[3];

    float* out_ctx  = (float*)d_out;
    float* out_attn = (float*)d_out + (size_t)BATCH * SEQ * DIM;

    cudaFuncSetAttribute(attn_mma_kernel,
                         cudaFuncAttributeMaxDynamicSharedMemorySize, SMEM_BYTES);

    dim3 grid(SEQ / TM, BATCH);
    attn_mma_kernel<<<grid, NTHR, SMEM_BYTES>>>(key, query, value, qmask,
                                                out_ctx, out_attn);
}

// round 13
// speedup vs baseline: 1.3067x; 1.1259x over previous
#include <cuda_runtime.h>
#include <cstdint>

#define BATCH 8
#define SEQ   2048
#define DIM   64
#define TM    64
#define TN    32
#define NTILES (SEQ/TN)   // 64
#define NTHR  256

// ---- smem layout (float offsets) ----
#define KST  68
#define VST  72
#define EST  36
#define KBUF (TN*KST)            // 2176
#define VBUF (TN*VST)            // 2304
#define F_KHI 0
#define F_KLO (F_KHI + 2*KBUF)   // 4352
#define F_VHI (F_KLO + 2*KBUF)   // 8704
#define F_VLO (F_VHI + 2*VBUF)   // 13312
#define F_SE  (F_VLO + 2*VBUF)   // 17920
#define F_MSK (F_SE + TM*EST)    // 20224
#define F_RS  (F_MSK + SEQ)      // 22272 (64 q x 2 halves)
#define F_INV (F_RS + 2*TM)      // 22400
#define SMEM_FLOATS (F_INV + TM) // 22464
#define SMEM_BYTES (SMEM_FLOATS*4)

// pre-split hi/lo scratch (16MB)
__device__ float g_khi[BATCH*SEQ*DIM];
__device__ float g_klo[BATCH*SEQ*DIM];
__device__ float g_vhi[BATCH*SEQ*DIM];
__device__ float g_vlo[BATCH*SEQ*DIM];

__device__ __forceinline__ uint32_t tf32u(float x) {
    uint32_t u; asm("cvt.rna.tf32.f32 %0, %1;" : "=r"(u) : "f"(x)); return u;
}
__device__ __forceinline__ float uf(uint32_t u) { return __uint_as_float(u); }
__device__ __forceinline__ uint32_t fu(float f) { return __float_as_uint(f); }
__device__ __forceinline__ uint32_t s2u(const void* p) {
    uint32_t a;
    asm("{ .reg .u64 t; cvta.to.shared.u64 t, %1; cvt.u32.u64 %0, t; }" : "=r"(a) : "l"(p));
    return a;
}

#define CP16(dst, src) asm volatile("cp.async.ca.shared.global [%0], [%1], 16;" \
                                    :: "r"(dst), "l"(src) : "memory")
#define CP_COMMIT() asm volatile("cp.async.commit_group;" ::: "memory")
#define CP_WAIT0()  asm volatile("cp.async.wait_group 0;" ::: "memory")

// D += A(16x8 tf32) * B(8x8 tf32), fp32 accumulate
__device__ __forceinline__ void mma8(float* c, const uint32_t* a, uint32_t b0, uint32_t b1) {
    asm volatile("mma.sync.aligned.m16n8k8.row.col.f32.tf32.tf32.f32 "
        "{%0,%1,%2,%3},{%4,%5,%6,%7},{%8,%9},{%0,%1,%2,%3};"
        : "+f"(c[0]), "+f"(c[1]), "+f"(c[2]), "+f"(c[3])
        : "r"(a[0]), "r"(a[1]), "r"(a[2]), "r"(a[3]), "r"(b0), "r"(b1));
}

// ---- prologue: split K,V into tf32-hi + fp32-lo in gmem ----
__global__ void __launch_bounds__(256)
split_kernel(const float* __restrict__ key, const float* __restrict__ value)
{
    int i = blockIdx.x * 256 + threadIdx.x;          // float4 index
    float4 k4 = ((const float4*)key)[i];
    float4 h, l;
    h.x = uf(tf32u(k4.x)); l.x = k4.x - h.x;
    h.y = uf(tf32u(k4.y)); l.y = k4.y - h.y;
    h.z = uf(tf32u(k4.z)); l.z = k4.z - h.z;
    h.w = uf(tf32u(k4.w)); l.w = k4.w - h.w;
    ((float4*)g_khi)[i] = h; ((float4*)g_klo)[i] = l;
    float4 v4 = ((const float4*)value)[i];
    h.x = uf(tf32u(v4.x)); l.x = v4.x - h.x;
    h.y = uf(tf32u(v4.y)); l.y = v4.y - h.y;
    h.z = uf(tf32u(v4.z)); l.z = v4.z - h.z;
    h.w = uf(tf32u(v4.w)); l.w = v4.w - h.w;
    ((float4*)g_vhi)[i] = h; ((float4*)g_vlo)[i] = l;
}

// stage pre-split tile nt (32 keys x 64 dims, 4 arrays) via cp.async
__device__ __forceinline__ void stage(uint32_t sb, size_t goff, int nt, int t) {
    const int buf = nt & 1;
    const size_t off = goff + (size_t)nt * TN * DIM;
    const float4* kh = (const float4*)(g_khi + off);
    const float4* kl = (const float4*)(g_klo + off);
    const float4* vh = (const float4*)(g_vhi + off);
    const float4* vl = (const float4*)(g_vlo + off);
    #pragma unroll
    for (int i = 0; i < 2; i++) {
        int idx = t + NTHR * i;              // float4 idx in 32x64 tile
        int row = idx >> 4, c = (idx & 15) * 4;
        CP16(sb + (F_KHI + buf*KBUF + row*KST + c)*4, kh + idx);
        CP16(sb + (F_KLO + buf*KBUF + row*KST + c)*4, kl + idx);
        CP16(sb + (F_VHI + buf*VBUF + row*VST + c)*4, vh + idx);
        CP16(sb + (F_VLO + buf*VBUF + row*VST + c)*4, vl + idx);
    }
}

__global__ void __launch_bounds__(NTHR, 2)
attn_mma_kernel(const float* __restrict__ query,
                const int*   __restrict__ qmask,
                float* __restrict__ out_ctx,
                float*              out_attn)
{
    extern __shared__ float sm[];
    const uint32_t sb = s2u(sm);
    const int b  = blockIdx.y;
    const int q0 = blockIdx.x * TM;
    const int t  = threadIdx.x;
    const int w  = t >> 5;
    const int wqg = w >> 1;          // q group 0..3 (16 rows each)
    const int kh  = w & 1;           // key half 0/1 (16 keys each)
    const int lane = t & 31;
    const int r4 = lane >> 2;        // 0..7
    const int c4 = lane & 3;         // 0..3

    const size_t goff = (size_t)b * SEQ * DIM;
    float* attn_base = out_attn + ((size_t)b * SEQ + q0) * SEQ;

    // ---- stage tile 0 (async), mask ----
    stage(sb, goff, 0, t);
    CP_COMMIT();
    {
        const int* mg = qmask + (size_t)b * SEQ;
        float* msk = sm + F_MSK;
        #pragma unroll
        for (int i = t; i < SEQ; i += NTHR)
            msk[i] = mg[i] ? -1e30f : 0.0f;
    }

    // ---- persistent Q frags (hi only, scaled 0.125) ----
    uint32_t qh[8][4];
    {
        const float* qr = query + ((size_t)b * SEQ + q0 + 16 * wqg) * DIM;
        #pragma unroll
        for (int ks = 0; ks < 8; ks++) {
            qh[ks][0] = tf32u(qr[(size_t)r4 * DIM + ks * 8 + c4] * 0.125f);
            qh[ks][1] = tf32u(qr[(size_t)(r4 + 8) * DIM + ks * 8 + c4] * 0.125f);
            qh[ks][2] = tf32u(qr[(size_t)r4 * DIM + ks * 8 + c4 + 4] * 0.125f);
            qh[ks][3] = tf32u(qr[(size_t)(r4 + 8) * DIM + ks * 8 + c4 + 4] * 0.125f);
        }
    }

    float cacc[4][2][4];             // ctx^T partial over this key half
    #pragma unroll
    for (int mt = 0; mt < 4; mt++)
        #pragma unroll
        for (int nq = 0; nq < 2; nq++)
            #pragma unroll
            for (int i = 0; i < 4; i++) cacc[mt][nq][i] = 0.0f;
    float rs0 = 0.0f, rs8 = 0.0f;

    float* sE = sm + F_SE;
    const float* msk = sm + F_MSK;

    for (int kt = 0; kt < NTILES; kt++) {
        const int buf = kt & 1;
        CP_WAIT0();
        __syncthreads();             // tile kt visible; prev compute done
        if (kt + 1 < NTILES) {
            stage(sb, goff, kt + 1, t);
            CP_COMMIT();
        }

        // ---- QK^T: S[16q x 16key(half)], 2-term tf32 ----
        float sacc[2][4];
        #pragma unroll
        for (int nt = 0; nt < 2; nt++)
            #pragma unroll
            for (int i = 0; i < 4; i++) sacc[nt][i] = 0.0f;

        const float* kh_b = sm + F_KHI + buf * KBUF + (kh * 16 + r4) * KST + c4;
        const float* kl_b = sm + F_KLO + buf * KBUF + (kh * 16 + r4) * KST + c4;
        #pragma unroll
        for (int ks = 0; ks < 8; ks++) {
            #pragma unroll
            for (int nt = 0; nt < 2; nt++) {
                const float* ph = kh_b + nt * 8 * KST + ks * 8;
                const float* pl = kl_b + nt * 8 * KST + ks * 8;
                mma8(sacc[nt], qh[ks], fu(ph[0]), fu(ph[4]));
                mma8(sacc[nt], qh[ks], fu(pl[0]), fu(pl[4]));
            }
        }

        // ---- epilogue: exp+mask -> gmem + sE, rowsum ----
        {
            float* ar0 = attn_base + (size_t)(16 * wqg + r4) * SEQ + kt * TN;
            float* ar8 = ar0 + (size_t)8 * SEQ;
            float* se0 = sE + (16 * wqg + r4) * EST;
            float* se8 = se0 + 8 * EST;
            #pragma unroll
            for (int nt = 0; nt < 2; nt++) {
                int kloc = kh * 16 + nt * 8 + 2 * c4;
                float m0 = msk[kt * TN + kloc];
                float m1 = msk[kt * TN + kloc + 1];
                float e0 = __expf(sacc[nt][0] + m0);
                float e1 = __expf(sacc[nt][1] + m1);
                float e2 = __expf(sacc[nt][2] + m0);
                float e3 = __expf(sacc[nt][3] + m1);
                rs0 += e0 + e1; rs8 += e2 + e3;
                *(float2*)(ar0 + kloc) = make_float2(e0, e1);
                *(float2*)(ar8 + kloc) = make_float2(e2, e3);
                *(float2*)(se0 + kloc) = make_float2(e0, e1);
                *(float2*)(se8 + kloc) = make_float2(e2, e3);
            }
        }
        __syncwarp();

        // ---- PV (transposed, own key half): ctx^T += (Vhi+Vlo)^T * P^T ----
        {
            const float* vh_b = sm + F_VHI + buf * VBUF + (kh * 16 + c4) * VST + r4;
            const float* vl_b = sm + F_VLO + buf * VBUF + (kh * 16 + c4) * VST + r4;
            const float* se_b = sE + (16 * wqg + r4) * EST + kh * 16 + c4;
            #pragma unroll
            for (int ks = 0; ks < 2; ks++) {
                uint32_t bh[2][2];
                #pragma unroll
                for (int nq = 0; nq < 2; nq++) {
                    bh[nq][0] = tf32u(se_b[nq * 8 * EST + ks * 8]);
                    bh[nq][1] = tf32u(se_b[nq * 8 * EST + ks * 8 + 4]);
                }
                #pragma unroll
                for (int mt = 0; mt < 4; mt++) {
                    const float* ah_p = vh_b + ks * 8 * VST + mt * 16;
                    const float* al_p = vl_b + ks * 8 * VST + mt * 16;
                    uint32_t ah[4], al[4];
                    ah[0] = fu(ah_p[0]);           al[0] = fu(al_p[0]);
                    ah[1] = fu(ah_p[8]);           al[1] = fu(al_p[8]);
                    ah[2] = fu(ah_p[4 * VST]);     al[2] = fu(al_p[4 * VST]);
                    ah[3] = fu(ah_p[4 * VST + 8]); al[3] = fu(al_p[4 * VST + 8]);
                    #pragma unroll
                    for (int nq = 0; nq < 2; nq++) {
                        mma8(cacc[mt][nq], ah, bh[nq][0], bh[nq][1]);
                        mma8(cacc[mt][nq], al, bh[nq][0], bh[nq][1]);
                    }
                }
            }
        }
    }
    __syncthreads();

    // ---- rowsum: quad-reduce, write per-half partials ----
    rs0 += __shfl_xor_sync(0xffffffffu, rs0, 1);
    rs0 += __shfl_xor_sync(0xffffffffu, rs0, 2);
    rs8 += __shfl_xor_sync(0xffffffffu, rs8, 1);
    rs8 += __shfl_xor_sync(0xffffffffu, rs8, 2);
    if (c4 == 0) {
        sm[F_RS + (16 * wqg + r4) * 2 + kh]     = rs0;
        sm[F_RS + (16 * wqg + r4 + 8) * 2 + kh] = rs8;
    }
    // ---- odd warps dump ctx partials (reuse K area) ----
    if (kh == 1) {
        float* dst = sm + F_KHI + wqg * 1024 + lane * 32;
        #pragma unroll
        for (int mt = 0; mt < 4; mt++)
            #pragma unroll
            for (int nq = 0; nq < 2; nq++)
                #pragma unroll
                for (int i = 0; i < 4; i++)
                    dst[mt * 8 + nq * 4 + i] = cacc[mt][nq][i];
    }
    __syncthreads();

    if (t < TM) sm[F_INV + t] = 1.0f / (sm[F_RS + t * 2] + sm[F_RS + t * 2 + 1]);
    if (kh == 0) {
        const float* src = sm + F_KHI + wqg * 1024 + lane * 32;
        #pragma unroll
        for (int mt = 0; mt < 4; mt++)
            #pragma unroll
            for (int nq = 0; nq < 2; nq++)
                #pragma unroll
                for (int i = 0; i < 4; i++)
                    cacc[mt][nq][i] += src[mt * 8 + nq * 4 + i];
    }
    __syncthreads();

    // ---- ctx out (even warps, normalized) ----
    if (kh == 0) {
        const float* sInv = sm + F_INV;
        #pragma unroll
        for (int nq = 0; nq < 2; nq++) {
            int qloc = 16 * wqg + nq * 8 + 2 * c4;
            float i0 = sInv[qloc], i1 = sInv[qloc + 1];
            float* o0 = out_ctx + ((size_t)b * SEQ + q0 + qloc) * DIM;
            float* o1 = o0 + DIM;
            #pragma unroll
            for (int mt = 0; mt < 4; mt++) {
                int dimr = mt * 16 + r4;
                o0[dimr]     = cacc[mt][nq][0] * i0;
                o1[dimr]     = cacc[mt][nq][1] * i1;
                o0[dimr + 8] = cacc[mt][nq][2] * i0;
                o1[dimr + 8] = cacc[mt][nq][3] * i1;
            }
        }
    }

    // ---- normalize this CTA's attn slab in place (L2-hot) ----
    {
        const float* sInv = sm + F_INV;
        #pragma unroll 4
        for (int i = t; i < TM * SEQ / 4; i += NTHR) {
            int r = i >> 9;            // / (SEQ/4)
            int c = i & 511;
            float inv = sInv[r];
            float4* p = (float4*)(attn_base + (size_t)r * SEQ) + c;
            float4 v = *p;
            v.x *= inv; v.y *= inv; v.z *= inv; v.w *= inv;
            *p = v;
        }
    }
}

extern "C" void kernel_launch(void* const* d_in, const int* in_sizes, int n_in,
                              void* d_out, int out_size)
{
    const float* key   = (const float*)d_in[0];
    const float* query = (const float*)d_in[1];
    const float* value = (const float*)d_in[2];
    const int*   qmask = (const int*)d_in[3];

    float* out_ctx  = (float*)d_out;
    float* out_attn = (float*)d_out + (size_t)BATCH * SEQ * DIM;

    split_kernel<<<BATCH*SEQ*DIM/4/256, 256>>>(key, value);

    cudaFuncSetAttribute(attn_mma_kernel,
                         cudaFuncAttributeMaxDynamicSharedMemorySize, SMEM_BYTES);
    dim3 grid(SEQ / TM, BATCH);
    attn_mma_kernel<<<grid, NTHR, SMEM_BYTES>>>(query, qmask, out_ctx, out_attn);
}